// round 9
// baseline (speedup 1.0000x reference)
#include <cuda_runtime.h>

// LinearDynamicalSystem: y[t] = b0*u[t] + b1*u[t-1] - f1*y[t-1] - f2*y[t-2]
// Single fused kernel, chunked parallel scan with decoupled lookback.
//   state s = (y[t], y[t-1]),  s' = M s + e1*v,  M = [[-f1,-f2],[1,0]]
//   per chunk:  s_end = A s_start + c,  A = M^L  (L = 128 = 2^7, by squaring)
//   c computed by Horner:  c <- M c + e1 v[k]   (k = 0..L-1)
// Lookback is warp-parallel: warp 0 polls 32 predecessor flags per round.
//
// Inputs (metadata order):
//   d_in[0] b_coeff (2,) f32
//   d_in[1] f_coeff (2,) f32
//   d_in[2] u_in    (N, B) f32, row-major
//   d_in[3] y_init  (B, 2) f32  -> [y[-1], y[-2]]
//   d_in[4] u_init  (B, 1) f32  -> [u[-1]]
// Output: (N, B) f32

#define CHUNK_L   128
#define LOG2_L    7
#define TPB       128            // threads per block
#define VEC       4              // batch columns per thread (float4)
#define TILE_B    (TPB * VEC)    // 512 batch columns per tile
#define MAX_CHUNK 64
#define MAX_B     2048
#define MAX_TILE  (MAX_B / TILE_B)

static_assert(CHUNK_L == (1 << LOG2_L), "CHUNK_L must be 2^LOG2_L");

// Scratch (static device arrays — no allocation).
__device__ float2   g_C[MAX_CHUNK * MAX_B];        // per-chunk aggregate (per column)
__device__ float2   g_I[MAX_CHUNK * MAX_B];        // per-chunk inclusive state
__device__ unsigned g_flag[MAX_CHUNK * MAX_TILE];  // 0=none, 1=aggregate, 2=inclusive

// ---------------------------------------------------------------------------
__global__ void lds_reset(int nflags)
{
    int i = blockIdx.x * blockDim.x + threadIdx.x;
    if (i < nflags) g_flag[i] = 0u;
}

// ---------------------------------------------------------------------------
// B_CT > 0: compile-time batch width (strength-reduced addressing).
// B_CT == 0: generic runtime fallback.
template <int B_CT>
__global__ void __launch_bounds__(TPB) lds_fused(
    const float* __restrict__ u,
    const float* __restrict__ u_init,
    const float* __restrict__ y_init,
    const float* __restrict__ bc,
    const float* __restrict__ fc,
    float* __restrict__ out,
    int B_rt, int nchunk, int ntile)
{
    const int B = (B_CT > 0) ? B_CT : B_rt;

    __shared__ int s_anchor;

    const int tid   = threadIdx.x;
    const int chunk = blockIdx.x / ntile;    // chunk-major: low bid = low chunk
    const int tile  = blockIdx.x % ntile;
    const int gb    = tile * TILE_B + tid * VEC;   // first of VEC batch columns

    const float b0 = bc[0], b1 = bc[1];
    const float f1 = fc[0], f2 = fc[1];

    // A = M^L by repeated squaring (7 iters). Identical fmaf sequence in every
    // thread/block => A is bitwise-uniform chip-wide (determinism of lookback).
    float a11, a12, a21, a22;
    {
        float m11 = -f1, m12 = -f2, m21 = 1.f, m22 = 0.f;
#pragma unroll
        for (int it = 0; it < LOG2_L; ++it) {
            const float t11 = fmaf(m11, m11, m12 * m21);
            const float t12 = fmaf(m11, m12, m12 * m22);
            const float t21 = fmaf(m21, m11, m22 * m21);
            const float t22 = fmaf(m21, m12, m22 * m22);
            m11 = t11; m12 = t12; m21 = t21; m22 = t22;
        }
        a11 = m11; a12 = m12; a21 = m21; a22 = m22;
    }

    const int rowstride = B / VEC;               // float4 elements per row
    const float4* __restrict__ up =
        (const float4*)(u) + (long)chunk * CHUNK_L * rowstride + (gb / VEC);

    // u[-1] for the VEC columns
    float4 u_prev0;
    if (chunk == 0) u_prev0 = *(const float4*)(u_init + gb);
    else            u_prev0 = up[-rowstride];

    // ---- Loop 1: chunk aggregate via Horner: c <- M c + e1 v[k] ------------
    float4 c1 = make_float4(0.f, 0.f, 0.f, 0.f);
    float4 c2 = make_float4(0.f, 0.f, 0.f, 0.f);
    {
        float4 upv = u_prev0;
#pragma unroll 8
        for (int k = 0; k < CHUNK_L; ++k) {
            const float4 ut = up[k * rowstride];
            {
                const float v = fmaf(b0, ut.x, b1 * upv.x);
                const float n = fmaf(-f1, c1.x, fmaf(-f2, c2.x, v));
                c2.x = c1.x; c1.x = n;
            }
            {
                const float v = fmaf(b0, ut.y, b1 * upv.y);
                const float n = fmaf(-f1, c1.y, fmaf(-f2, c2.y, v));
                c2.y = c1.y; c1.y = n;
            }
            {
                const float v = fmaf(b0, ut.z, b1 * upv.z);
                const float n = fmaf(-f1, c1.z, fmaf(-f2, c2.z, v));
                c2.z = c1.z; c1.z = n;
            }
            {
                const float v = fmaf(b0, ut.w, b1 * upv.w);
                const float n = fmaf(-f1, c1.w, fmaf(-f2, c2.w, v));
                c2.w = c1.w; c1.w = n;
            }
            upv = ut;
        }
    }

    // ---- Decoupled lookback: recover exact chunk start state ---------------
    float sx0, sx1, sx2, sx3, sy0, sy1, sy2, sy3;

    if (chunk > 0) {
        // Publish aggregate (flag=1); no waiting happened before this point.
        {
            float4* dst = (float4*)&g_C[chunk * B + gb];     // 4 float2 = 2 float4
            __stcg(dst + 0, make_float4(c1.x, c2.x, c1.y, c2.y));
            __stcg(dst + 1, make_float4(c1.z, c2.z, c1.w, c2.w));
        }
        __threadfence();                         // release: data before flag
        __syncthreads();

        // Warp-parallel windowed lookback (warp 0). Lane l polls chunk base-l.
        // Each round confirms 32 predecessor aggregates at once; ballot finds
        // the nearest inclusive. Worst case ceil(chunk/32) rounds instead of
        // `chunk` serial polls.
        if (tid < 32) {
            if (tid == 0)
                atomicExch(&g_flag[chunk * ntile + tile], 1u);

            int anchor = -1;
            for (int base = chunk - 1; base >= 0; base -= 32) {
                const int  j     = base - tid;
                const bool valid = (j >= 0);
                unsigned   st    = 0u;
                do {
                    if (valid && st == 0u)
                        st = atomicAdd(&g_flag[j * ntile + tile], 0u);
                } while (__any_sync(0xffffffffu, valid && st == 0u));
                const unsigned incl = __ballot_sync(0xffffffffu, valid && st == 2u);
                if (incl) { anchor = base - (__ffs(incl) - 1); break; }
            }
            if (tid == 0) s_anchor = anchor;
        }
        __syncthreads();
        __threadfence();                         // acquire: flags before data reads
        const int anchor = s_anchor;

        if (anchor >= 0) {
            const float4* src = (const float4*)&g_I[anchor * B + gb];
            const float4 p0  = __ldcg(src + 0);
            const float4 p1v = __ldcg(src + 1);
            sx0 = p0.x;  sy0 = p0.y;  sx1 = p0.z;  sy1 = p0.w;
            sx2 = p1v.x; sy2 = p1v.y; sx3 = p1v.z; sy3 = p1v.w;
        } else {
            const float4 q0 = *(const float4*)(y_init + 2 * gb);
            const float4 q1 = *(const float4*)(y_init + 2 * gb + 4);
            sx0 = q0.x; sy0 = q0.y; sx1 = q0.z; sy1 = q0.w;
            sx2 = q1.x; sy2 = q1.y; sx3 = q1.z; sy3 = q1.w;
        }
        // Forward Horner over remaining aggregates: s = A s + c_j
        // (Identical fmaf sequence in every block => states are
        //  anchor-independent bitwise => deterministic across replays.)
        for (int j = anchor + 1; j < chunk; ++j) {
            const float4* src = (const float4*)&g_C[j * B + gb];
            const float4 p0  = __ldcg(src + 0);
            const float4 p1v = __ldcg(src + 1);
            float nx, ny;
            nx = fmaf(a11, sx0, fmaf(a12, sy0, p0.x));
            ny = fmaf(a21, sx0, fmaf(a22, sy0, p0.y));  sx0 = nx; sy0 = ny;
            nx = fmaf(a11, sx1, fmaf(a12, sy1, p0.z));
            ny = fmaf(a21, sx1, fmaf(a22, sy1, p0.w));  sx1 = nx; sy1 = ny;
            nx = fmaf(a11, sx2, fmaf(a12, sy2, p1v.x));
            ny = fmaf(a21, sx2, fmaf(a22, sy2, p1v.y)); sx2 = nx; sy2 = ny;
            nx = fmaf(a11, sx3, fmaf(a12, sy3, p1v.z));
            ny = fmaf(a21, sx3, fmaf(a22, sy3, p1v.w)); sx3 = nx; sy3 = ny;
        }
    } else {
        const float4 q0 = *(const float4*)(y_init + 2 * gb);
        const float4 q1 = *(const float4*)(y_init + 2 * gb + 4);
        sx0 = q0.x; sy0 = q0.y; sx1 = q0.z; sy1 = q0.w;
        sx2 = q1.x; sy2 = q1.y; sx3 = q1.z; sy3 = q1.w;
    }

    // ---- Publish inclusive state so successors shortcut --------------------
    if (chunk < nchunk - 1) {
        float4* dst = (float4*)&g_I[chunk * B + gb];
        const float ix0 = fmaf(a11, sx0, fmaf(a12, sy0, c1.x));
        const float iy0 = fmaf(a21, sx0, fmaf(a22, sy0, c2.x));
        const float ix1 = fmaf(a11, sx1, fmaf(a12, sy1, c1.y));
        const float iy1 = fmaf(a21, sx1, fmaf(a22, sy1, c2.y));
        const float ix2 = fmaf(a11, sx2, fmaf(a12, sy2, c1.z));
        const float iy2 = fmaf(a21, sx2, fmaf(a22, sy2, c2.z));
        const float ix3 = fmaf(a11, sx3, fmaf(a12, sy3, c1.w));
        const float iy3 = fmaf(a21, sx3, fmaf(a22, sy3, c2.w));
        __stcg(dst + 0, make_float4(ix0, iy0, ix1, iy1));
        __stcg(dst + 1, make_float4(ix2, iy2, ix3, iy3));
        __threadfence();                         // release
        __syncthreads();
        if (tid == 0) atomicExch(&g_flag[chunk * ntile + tile], 2u);
    }

    // ---- Loop 2: exact replay from known start state -----------------------
    // u re-read hits L2 (loaded by loop 1 of this same kernel); evict-first.
    float4* op = (float4*)(out) + (long)chunk * CHUNK_L * rowstride + (gb / VEC);
    {
        float4 upv = u_prev0;
        float y1x = sx0, y2x = sy0, y1y = sx1, y2y = sy1;
        float y1z = sx2, y2z = sy2, y1w = sx3, y2w = sy3;
#pragma unroll 8
        for (int k = 0; k < CHUNK_L; ++k) {
            const float4 ut = __ldcs(up + k * rowstride);
            float4 yo;
            {
                const float v = fmaf(b0, ut.x, b1 * upv.x);
                yo.x = fmaf(-f1, y1x, fmaf(-f2, y2x, v));
                y2x = y1x; y1x = yo.x;
            }
            {
                const float v = fmaf(b0, ut.y, b1 * upv.y);
                yo.y = fmaf(-f1, y1y, fmaf(-f2, y2y, v));
                y2y = y1y; y1y = yo.y;
            }
            {
                const float v = fmaf(b0, ut.z, b1 * upv.z);
                yo.z = fmaf(-f1, y1z, fmaf(-f2, y2z, v));
                y2z = y1z; y1z = yo.z;
            }
            {
                const float v = fmaf(b0, ut.w, b1 * upv.w);
                yo.w = fmaf(-f1, y1w, fmaf(-f2, y2w, v));
                y2w = y1w; y1w = yo.w;
            }
            __stcs(op + k * rowstride, yo);
            upv = ut;
        }
    }
}

// ---------------------------------------------------------------------------
extern "C" void kernel_launch(void* const* d_in, const int* in_sizes, int n_in,
                              void* d_out, int out_size)
{
    const float* bc     = (const float*)d_in[0];
    const float* fc     = (const float*)d_in[1];
    const float* u      = (const float*)d_in[2];
    const float* y_init = (const float*)d_in[3];
    const float* u_init = (const float*)d_in[4];
    float* out = (float*)d_out;

    const int B      = in_sizes[3] / 2;      // y_init is (B, 2)
    const int N      = in_sizes[2] / B;      // u_in is (N, B)
    const int nchunk = N / CHUNK_L;          // 8192/128 = 64
    const int ntile  = B / TILE_B;           // 2048/512 = 4
    const int nflags = nchunk * ntile;       // 256

    lds_reset<<<(nflags + 255) / 256, 256>>>(nflags);

    if (B == 2048) {
        lds_fused<2048><<<nchunk * ntile, TPB>>>(u, u_init, y_init, bc, fc, out,
                                                 B, nchunk, ntile);
    } else {
        lds_fused<0><<<nchunk * ntile, TPB>>>(u, u_init, y_init, bc, fc, out,
                                              B, nchunk, ntile);
    }
}